// round 12
// baseline (speedup 1.0000x reference)
#include <cuda_runtime.h>

// Problem constants
#define HH   64
#define WW   64
#define CIN  48
#define OCC  192   // 4*F gate channels
#define BB   4
#define TT   16
#define NF   48

#define PATCH_F  4800   // 10*10*48 patch
#define WSLICE_F 9216   // 48*192 weight slice
// L1 role: s_in @0 (4800) + s_w @4800 (9216) = 14016 floats
// L2 role: s_inA @0, s_inB @4800, s_w @9600..18816
#define SMEM_FLOATS 18816
#define SMEM_BYTES  (SMEM_FLOATS * 4)
#define CONVX_SMEM_BYTES ((PATCH_F + WSLICE_F) * 4)

typedef unsigned long long u64;

// Scratch (device globals -- no runtime allocation allowed)
__device__ float g_zx [(size_t)BB * TT * HH * WW * OCC];  // conv(x,Wx1)+b1 for all frames
__device__ float g_h1 [(size_t)BB * TT * HH * WW * NF];   // layer-1 output sequence
__device__ float g_hA [(size_t)BB * HH * WW * NF];        // L1 recurrent h (double-buffered)
__device__ float g_hB [(size_t)BB * HH * WW * NF];
__device__ float g_c1 [(size_t)BB * HH * WW * NF];        // L1 cell state
__device__ float g_h2A[(size_t)BB * HH * WW * NF];        // L2 recurrent h
__device__ float g_h2B[(size_t)BB * HH * WW * NF];
__device__ float g_c2 [(size_t)BB * HH * WW * NF];        // L2 cell state

__global__ void zero_state_kernel() {
    size_t n = (size_t)BB * HH * WW * NF;
    for (size_t i = (size_t)blockIdx.x * blockDim.x + threadIdx.x; i < n;
         i += (size_t)gridDim.x * blockDim.x) {
        g_hA[i] = 0.f;  g_c1[i] = 0.f;
        g_h2A[i] = 0.f; g_c2[i] = 0.f;
    }
}

__device__ __forceinline__ float hsig(float x) {
    return __saturatef(x * (1.0f / 6.0f) + 0.5f);
}

// ---- packed f32x2 helpers (Blackwell FFMA2) ----
__device__ __forceinline__ u64 bcast2(float x) {
    u64 r;
    asm("mov.b64 %0, {%1, %1};" : "=l"(r) : "f"(x));
    return r;
}
__device__ __forceinline__ void ffma2(u64& d, u64 a, u64 b) {
    asm("fma.rn.f32x2 %0, %1, %2, %0;" : "+l"(d) : "l"(a), "l"(b));
}

// Load 10x10x48 patch (zero-padded) into smem; optional BN on in-bounds pixels only.
template <bool BN>
__device__ __forceinline__ void load_patch(const float* __restrict__ src,
                                           float* s_in, int gy0, int gx0, int tid,
                                           const float* s_scale, const float* s_shift) {
    for (int p = tid; p < 1200; p += 256) {  // 100 pixels * 12 float4
        int pix = p / 12, cv = p - pix * 12;
        int py = pix / 10, px = pix - py * 10;
        int gy = gy0 + py, gx = gx0 + px;
        float4 v = make_float4(0.f, 0.f, 0.f, 0.f);
        if ((unsigned)gy < HH && (unsigned)gx < WW) {
            v = *(const float4*)(src + ((size_t)gy * WW + gx) * CIN + cv * 4);
            if (BN) {
                int c = cv * 4;
                v.x = v.x * s_scale[c + 0] + s_shift[c + 0];
                v.y = v.y * s_scale[c + 1] + s_shift[c + 1];
                v.z = v.z * s_scale[c + 2] + s_shift[c + 2];
                v.w = v.w * s_scale[c + 3] + s_shift[c + 3];
            }
        }
        ((float4*)s_in)[p] = v;
    }
}

// 3x3x48->192 conv accumulate for one weight tensor over one patch.
// Thread og owns oc pairs {32j+2og}; weight LDS.64 conflict-free; inputs via LDS.128.
__device__ __forceinline__ void conv9(const float* __restrict__ Wg,  // [3,3,48,192]
                                      const float* s_in, float* s_w,
                                      u64 acc[4][6], int tid, int sy, int sx0, int og) {
#pragma unroll 1
    for (int kk = 0; kk < 9; kk++) {
        __syncthreads();
        const float4* wsrc = (const float4*)(Wg + (size_t)kk * WSLICE_F);
        float4* wdst = (float4*)s_w;
#pragma unroll
        for (int p = 0; p < 9; p++) wdst[tid + p * 256] = wsrc[tid + p * 256];
        __syncthreads();

        int kh = kk / 3, kw = kk - kh * 3;
        const float* base = s_in + ((sy + kh) * 10 + sx0 + kw) * CIN;
        const float* wcol = s_w + 2 * og;
#pragma unroll 1
        for (int c4 = 0; c4 < 12; c4++) {
            float4 q0 = *(const float4*)(base + 0 * CIN + 4 * c4);
            float4 q1 = *(const float4*)(base + 1 * CIN + 4 * c4);
            float4 q2 = *(const float4*)(base + 2 * CIN + 4 * c4);
            float4 q3 = *(const float4*)(base + 3 * CIN + 4 * c4);
            const u64* w2 = (const u64*)(wcol + 4 * c4 * OCC);
#pragma unroll
            for (int cc = 0; cc < 4; cc++) {
                u64 wv[6];
#pragma unroll
                for (int j = 0; j < 6; j++) wv[j] = w2[cc * 96 + 16 * j];
                float f0 = cc == 0 ? q0.x : cc == 1 ? q0.y : cc == 2 ? q0.z : q0.w;
                float f1 = cc == 0 ? q1.x : cc == 1 ? q1.y : cc == 2 ? q1.z : q1.w;
                float f2 = cc == 0 ? q2.x : cc == 1 ? q2.y : cc == 2 ? q2.z : q2.w;
                float f3 = cc == 0 ? q3.x : cc == 1 ? q3.y : cc == 2 ? q3.z : q3.w;
                u64 a0 = bcast2(f0), a1 = bcast2(f1), a2 = bcast2(f2), a3 = bcast2(f3);
#pragma unroll
                for (int j = 0; j < 6; j++) {
                    ffma2(acc[0][j], a0, wv[j]);
                    ffma2(acc[1][j], a1, wv[j]);
                    ffma2(acc[2][j], a2, wv[j]);
                    ffma2(acc[3][j], a3, wv[j]);
                }
            }
        }
    }
}

// conv(x, Wx1) + b1 over all 64 (b,t) frames -> g_zx
__global__ void __launch_bounds__(256, 3) convx_kernel(
    const float* __restrict__ xin, const float* __restrict__ Wx,
    const float* __restrict__ bias) {
    extern __shared__ float sm[];
    float* s_in = sm;
    float* s_w  = sm + PATCH_F;

    int tid = threadIdx.x;
    int img = blockIdx.z;
    int gy0 = blockIdx.y * 8 - 1, gx0 = blockIdx.x * 8 - 1;

    load_patch<false>(xin + (size_t)img * HH * WW * CIN, s_in, gy0, gx0, tid,
                      nullptr, nullptr);

    int og = tid & 15, sg = tid >> 4;
    int sy = sg >> 1, sx0 = (sg & 1) * 4;

    u64 acc[4][6];
    {
        const float* bp = bias + 2 * og;
#pragma unroll
        for (int j = 0; j < 6; j++) {
            u64 bv = *(const u64*)(bp + 32 * j);
            acc[0][j] = bv; acc[1][j] = bv; acc[2][j] = bv; acc[3][j] = bv;
        }
    }
    conv9(Wx, s_in, s_w, acc, tid, sy, sx0, og);

#pragma unroll
    for (int i = 0; i < 4; i++) {
        int y = blockIdx.y * 8 + sy, x = blockIdx.x * 8 + sx0 + i;
        float* dst = g_zx + (((size_t)img * HH + y) * WW + x) * OCC + 2 * og;
#pragma unroll
        for (int j = 0; j < 6; j++)
            *(u64*)(dst + 32 * j) = acc[i][j];
    }
}

// Combined launch at time index t:
//   role 0 (blockIdx.z < 4):  L1 step t   (skip if t >= 16)
//   role 1 (blockIdx.z >= 4): L2 step t-1 (skip if t == 0); Zx-conv + BN fused in.
__global__ void __launch_bounds__(256, 3) combo_kernel(
    int t,
    const float* __restrict__ Wh1,
    const float* __restrict__ Wx2, const float* __restrict__ Wh2,
    const float* __restrict__ b2,
    const float* __restrict__ gamma, const float* __restrict__ beta,
    const float* __restrict__ mean, const float* __restrict__ var,
    const float* __restrict__ xres, float* __restrict__ out) {
    extern __shared__ float sm[];
    int tid = threadIdx.x;
    int b = blockIdx.z & 3, role = blockIdx.z >> 2;
    int gy0 = blockIdx.y * 8 - 1, gx0 = blockIdx.x * 8 - 1;
    int og = tid & 15, sg = tid >> 4;
    int sy = sg >> 1, sx0 = (sg & 1) * 4;

    u64 acc[4][6];
    float* s_z = sm;
    const float* cmem;  // cell state
    float* cmemw;
    float* houtp;
    const float* zxp = nullptr;   // L1: per-pixel zx base; L2: none
    int imgt;

    if (role == 0) {
        if (t >= TT) return;
        float* s_in = sm;
        float* s_w  = sm + PATCH_F;
        const float* hin = (t & 1) ? g_hB : g_hA;
        houtp            = (t & 1) ? g_hA : g_hB;
        cmemw = g_c1; cmem = g_c1;
        imgt = b * TT + t;
        zxp = g_zx + (size_t)imgt * HH * WW * OCC;

        load_patch<false>(hin + (size_t)b * HH * WW * NF, s_in, gy0, gx0, tid,
                          nullptr, nullptr);
#pragma unroll
        for (int i = 0; i < 4; i++)
#pragma unroll
            for (int j = 0; j < 6; j++) acc[i][j] = 0ull;

        conv9(Wh1, s_in, s_w, acc, tid, sy, sx0, og);
    } else {
        int s = t - 1;
        if (s < 0) return;
        __shared__ float s_scale[CIN], s_shift[CIN];
        if (tid < CIN) {
            float sc = gamma[tid] * rsqrtf(var[tid] + 1e-3f);
            s_scale[tid] = sc;
            s_shift[tid] = beta[tid] - mean[tid] * sc;
        }
        __syncthreads();

        float* s_inA = sm;              // bn(h1[s])
        float* s_inB = sm + PATCH_F;    // h2 state
        float* s_w   = sm + 2 * PATCH_F;
        const float* hin = (s & 1) ? g_h2B : g_h2A;
        houtp            = (s & 1) ? g_h2A : g_h2B;
        cmemw = g_c2; cmem = g_c2;
        imgt = b * TT + s;

        load_patch<true>(g_h1 + (size_t)imgt * HH * WW * NF, s_inA, gy0, gx0, tid,
                         s_scale, s_shift);
        load_patch<false>(hin + (size_t)b * HH * WW * NF, s_inB, gy0, gx0, tid,
                          nullptr, nullptr);
        {
            const float* bp = b2 + 2 * og;
#pragma unroll
            for (int j = 0; j < 6; j++) {
                u64 bv = *(const u64*)(bp + 32 * j);
                acc[0][j] = bv; acc[1][j] = bv; acc[2][j] = bv; acc[3][j] = bv;
            }
        }
        conv9(Wx2, s_inA, s_w, acc, tid, sy, sx0, og);
        conv9(Wh2, s_inB, s_w, acc, tid, sy, sx0, og);
    }

    // ---- z-phase: stash acc in smem, then fused gates ----
    __syncthreads();
#pragma unroll
    for (int i = 0; i < 4; i++) {
        int sp = sy * 8 + sx0 + i;
        float* dst = s_z + sp * OCC + 2 * og;
#pragma unroll
        for (int j = 0; j < 6; j++)
            *(u64*)(dst + 32 * j) = acc[i][j];  // banks 2og,2og+1: conflict-free
    }
    __syncthreads();

#pragma unroll 1
    for (int k = 0; k < 12; k++) {
        int e = tid + k * 256;         // 0..3071: 64 spatial x 48 f-channels
        int sp = e / 48, f = e - sp * 48;
        int yy = gy0 + 1 + (sp >> 3);
        int xx = gx0 + 1 + (sp & 7);

        float zi = s_z[sp * OCC + f];
        float zf = s_z[sp * OCC + f + NF];
        float zg = s_z[sp * OCC + f + 2 * NF];
        float zo = s_z[sp * OCC + f + 3 * NF];
        if (role == 0) {
            const float* zx = zxp + ((size_t)yy * WW + xx) * OCC;
            zi += zx[f]; zf += zx[f + NF]; zg += zx[f + 2 * NF]; zo += zx[f + 3 * NF];
        }

        size_t hoff = (((size_t)b * HH + yy) * WW + xx) * NF + f;
        float cold = cmem[hoff];
        float cn = hsig(zf) * cold + hsig(zi) * tanhf(zg);
        float hn = hsig(zo) * tanhf(cn);
        cmemw[hoff] = cn;
        houtp[hoff] = hn;

        size_t ooff = (((size_t)imgt * HH + yy) * WW + xx) * NF + f;
        if (role == 0)
            g_h1[ooff] = hn;
        else
            out[ooff] = xres[ooff] + hn;
    }
}

extern "C" void kernel_launch(void* const* d_in, const int* in_sizes, int n_in,
                              void* d_out, int out_size) {
    const float* x     = (const float*)d_in[0];
    const float* Wx1   = (const float*)d_in[1];
    const float* Wh1   = (const float*)d_in[2];
    const float* b1    = (const float*)d_in[3];
    const float* Wx2   = (const float*)d_in[4];
    const float* Wh2   = (const float*)d_in[5];
    const float* b2    = (const float*)d_in[6];
    const float* gamma = (const float*)d_in[7];
    const float* beta  = (const float*)d_in[8];
    const float* mean  = (const float*)d_in[9];
    const float* var   = (const float*)d_in[10];
    float* out = (float*)d_out;

    cudaFuncSetAttribute((const void*)convx_kernel,
                         cudaFuncAttributeMaxDynamicSharedMemorySize, CONVX_SMEM_BYTES);
    cudaFuncSetAttribute((const void*)combo_kernel,
                         cudaFuncAttributeMaxDynamicSharedMemorySize, SMEM_BYTES);

    dim3 blk(256);
    dim3 gridx(8, 8, BB * TT);  // zx for all frames
    dim3 gridc(8, 8, 2 * BB);   // L1 + L2 roles

    zero_state_kernel<<<256, 256>>>();
    convx_kernel<<<gridx, blk, CONVX_SMEM_BYTES>>>(x, Wx1, b1);

    for (int t = 0; t <= TT; t++)
        combo_kernel<<<gridc, blk, SMEM_BYTES>>>(t, Wh1, Wx2, Wh2, b2,
                                                 gamma, beta, mean, var, x, out);
}

// round 14
// speedup vs baseline: 1.3121x; 1.3121x over previous
#include <cuda_runtime.h>

// Problem constants
#define HH   64
#define WW   64
#define CIN  48
#define OCC  192   // 4*F gate channels
#define BB   4
#define TT   16
#define NF   48

// Dynamic smem: max( patch 10*10*48 + weights 48*192 , z 64*192 ) floats
#define SMEM_FLOATS 14016
#define SMEM_BYTES  (SMEM_FLOATS * 4)

typedef unsigned long long u64;

// Scratch (device globals -- no runtime allocation allowed)
__device__ float g_zx[(size_t)BB * TT * HH * WW * OCC];  // precomputed conv(x,Wx)+b per layer
__device__ float g_h1[(size_t)BB * TT * HH * WW * NF];   // layer-1 output sequence
__device__ float g_hA[(size_t)BB * HH * WW * NF];        // recurrent h (double-buffered)
__device__ float g_hB[(size_t)BB * HH * WW * NF];
__device__ float g_c [(size_t)BB * HH * WW * NF];        // cell state

__global__ void zero_state_kernel() {
    size_t n = (size_t)BB * HH * WW * NF;
    for (size_t i = (size_t)blockIdx.x * blockDim.x + threadIdx.x; i < n;
         i += (size_t)gridDim.x * blockDim.x) {
        g_hA[i] = 0.f;
        g_c[i]  = 0.f;
    }
}

__device__ __forceinline__ float hsig(float x) {
    return __saturatef(x * (1.0f / 6.0f) + 0.5f);
}

// ---- packed f32x2 helpers (Blackwell FFMA2: 128-lane fp32 path) ----
__device__ __forceinline__ u64 bcast2(float x) {
    u64 r;
    asm("mov.b64 %0, {%1, %1};" : "=l"(r) : "f"(x));
    return r;
}
__device__ __forceinline__ void ffma2(u64& d, u64 a, u64 b) {
    asm("fma.rn.f32x2 %0, %1, %2, %0;" : "+l"(d) : "l"(a), "l"(b));
}

// Load 10x10x48 input patch (zero-padded) into smem, optionally applying BN.
// BN applies ONLY to in-bounds pixels -- padding of the normalized tensor is exact zero.
template <bool BN>
__device__ __forceinline__ void load_patch(const float* __restrict__ src,  // image base [H,W,48]
                                           float* s_in, int gy0, int gx0, int tid,
                                           const float* s_scale, const float* s_shift) {
    for (int p = tid; p < 1200; p += 256) {  // 100 pixels * 12 float4
        int pix = p / 12, cv = p - pix * 12;
        int py = pix / 10, px = pix - py * 10;
        int gy = gy0 + py, gx = gx0 + px;
        float4 v = make_float4(0.f, 0.f, 0.f, 0.f);
        if ((unsigned)gy < HH && (unsigned)gx < WW) {
            v = *(const float4*)(src + ((size_t)gy * WW + gx) * CIN + cv * 4);
            if (BN) {
                int c = cv * 4;
                v.x = v.x * s_scale[c + 0] + s_shift[c + 0];
                v.y = v.y * s_scale[c + 1] + s_shift[c + 1];
                v.z = v.z * s_scale[c + 2] + s_shift[c + 2];
                v.w = v.w * s_scale[c + 3] + s_shift[c + 3];
            }
        }
        ((float4*)s_in)[p] = v;
    }
}

// ---- Scalar conv core (used by step kernels; known-good, latency-bound path) ----
// Accumulate 3x3x48 -> 192 for this thread's 4 spatial x 12 oc tile.
__device__ __forceinline__ void conv_accum(const float* __restrict__ Wg,  // [3,3,48,192]
                                           const float* s_in, float* s_w,
                                           float acc[4][12],
                                           int tid, int sy, int sx0, int oc0) {
#pragma unroll 1
    for (int kk = 0; kk < 9; kk++) {
        __syncthreads();
        const float4* wsrc = (const float4*)(Wg + (size_t)kk * CIN * OCC);
        float4* wdst = (float4*)s_w;
#pragma unroll
        for (int p = 0; p < 9; p++) wdst[tid + p * 256] = wsrc[tid + p * 256];
        __syncthreads();

        int kh = kk / 3, kw = kk - kh * 3;
        const float* inrow = s_in + ((sy + kh) * 10 + sx0 + kw) * CIN;
        const float* wbase = s_w + oc0;
#pragma unroll 4
        for (int c = 0; c < CIN; c++) {
            float iv0 = inrow[c];
            float iv1 = inrow[c + CIN];
            float iv2 = inrow[c + 2 * CIN];
            float iv3 = inrow[c + 3 * CIN];
            const float4* wc4 = (const float4*)(wbase + c * OCC);
            float4 wa = wc4[0], wb = wc4[1], wc = wc4[2];
            float wv[12] = {wa.x, wa.y, wa.z, wa.w, wb.x, wb.y, wb.z, wb.w,
                            wc.x, wc.y, wc.z, wc.w};
#pragma unroll
            for (int j = 0; j < 12; j++) {
                acc[0][j] += iv0 * wv[j];
                acc[1][j] += iv1 * wv[j];
                acc[2][j] += iv2 * wv[j];
                acc[3][j] += iv3 * wv[j];
            }
        }
    }
}

// ---- FFMA2 conv core (convx only; pipe-bound path, crossbar-light tile) ----
// Thread og (0..31) owns oc pairs {64j + 2og : j=0..2}; handles 8 px (row sy, x 0..7).
// Weight LDS.64: lanes og,og+16 2-way bank overlap -> 2 phases (fine).
__device__ __forceinline__ void conv_accum2(const float* __restrict__ Wg,  // [3,3,48,192]
                                            const float* s_in, float* s_w,
                                            u64 acc[8][3],
                                            int tid, int sy, int og) {
#pragma unroll 1
    for (int kk = 0; kk < 9; kk++) {
        __syncthreads();
        const float4* wsrc = (const float4*)(Wg + (size_t)kk * CIN * OCC);
        float4* wdst = (float4*)s_w;
#pragma unroll
        for (int p = 0; p < 9; p++) wdst[tid + p * 256] = wsrc[tid + p * 256];
        __syncthreads();

        int kh = kk / 3, kw = kk - kh * 3;
        const float* inrow = s_in + ((sy + kh) * 10 + kw) * CIN;  // px x: + x*CIN
        const float* wcol = s_w + 2 * og;
#pragma unroll 2
        for (int c = 0; c < CIN; c++) {
            const u64* w2 = (const u64*)(wcol + c * OCC);
            u64 w0 = w2[0], w1 = w2[32], w3 = w2[64];  // oc 2og+{0,64,128}
            u64 a[8];
#pragma unroll
            for (int x = 0; x < 8; x++) a[x] = bcast2(inrow[x * CIN + c]);
#pragma unroll
            for (int x = 0; x < 8; x++) {
                ffma2(acc[x][0], a[x], w0);
                ffma2(acc[x][1], a[x], w1);
                ffma2(acc[x][2], a[x], w3);
            }
        }
    }
}

// conv(input, Wx) + b over all 64 (b,t) images (FFMA2 core).
// BN=true reads g_h1 and applies BN first.
template <bool BN>
__global__ void __launch_bounds__(256, 3) convx_kernel(
    const float* __restrict__ xin, const float* __restrict__ Wx,
    const float* __restrict__ bias,
    const float* __restrict__ gamma, const float* __restrict__ beta,
    const float* __restrict__ mean, const float* __restrict__ var) {
    extern __shared__ float sm[];
    float* s_in = sm;          // 4800 floats
    float* s_w  = sm + 4800;   // 9216 floats
    __shared__ float s_scale[CIN], s_shift[CIN];

    int tid = threadIdx.x;
    int img = blockIdx.z;  // b*T + t
    int gy0 = blockIdx.y * 8 - 1, gx0 = blockIdx.x * 8 - 1;

    if (BN) {
        if (tid < CIN) {
            float sc = gamma[tid] * rsqrtf(var[tid] + 1e-3f);
            s_scale[tid] = sc;
            s_shift[tid] = beta[tid] - mean[tid] * sc;
        }
        __syncthreads();
    }
    const float* src = BN ? (g_h1 + (size_t)img * HH * WW * NF)
                          : (xin + (size_t)img * HH * WW * CIN);
    load_patch<BN>(src, s_in, gy0, gx0, tid, s_scale, s_shift);

    int og = tid & 31, sy = tid >> 5;  // sy 0..7: row; thread covers x 0..7

    u64 acc[8][3];
    {
        const float* bp = bias + 2 * og;
        u64 b0 = *(const u64*)(bp);
        u64 b1 = *(const u64*)(bp + 64);
        u64 b3 = *(const u64*)(bp + 128);
#pragma unroll
        for (int x = 0; x < 8; x++) {
            acc[x][0] = b0; acc[x][1] = b1; acc[x][2] = b3;
        }
    }
    conv_accum2(Wx, s_in, s_w, acc, tid, sy, og);

    int y = blockIdx.y * 8 + sy;
#pragma unroll
    for (int x = 0; x < 8; x++) {
        float* dst = g_zx + (((size_t)img * HH + y) * WW + blockIdx.x * 8 + x) * OCC + 2 * og;
        *(u64*)(dst)       = acc[x][0];
        *(u64*)(dst + 64)  = acc[x][1];
        *(u64*)(dst + 128) = acc[x][2];
    }
}

// One recurrent step (scalar core, unchanged from R4): z = zx[t] + conv(h,Wh); gates.
// LAYER 1 -> write h to g_h1 sequence; LAYER 2 -> write out = x + h.
template <int LAYER>
__global__ void __launch_bounds__(256, 2) step_kernel(
    const float* __restrict__ Wh, int t, int parity,
    const float* __restrict__ xres, float* __restrict__ out) {
    extern __shared__ float sm[];
    float* s_in = sm;
    float* s_w  = sm + 4800;
    float* s_z  = sm;  // reuses patch+weight region after conv

    int tid = threadIdx.x;
    int b = blockIdx.z;
    int gy0 = blockIdx.y * 8 - 1, gx0 = blockIdx.x * 8 - 1;

    const float* hin = parity ? g_hB : g_hA;
    float* hout      = parity ? g_hA : g_hB;

    load_patch<false>(hin + (size_t)b * HH * WW * NF, s_in, gy0, gx0, tid, nullptr, nullptr);

    int og = tid & 15, sg = tid >> 4;
    int oc0 = og * 12;
    int sy = sg >> 1, sx0 = (sg & 1) * 4;

    float acc[4][12];
#pragma unroll
    for (int i = 0; i < 4; i++)
#pragma unroll
        for (int j = 0; j < 12; j++) acc[i][j] = 0.f;

    conv_accum(Wh, s_in, s_w, acc, tid, sy, sx0, oc0);

    __syncthreads();  // all smem reads done; safe to overwrite with z
#pragma unroll
    for (int i = 0; i < 4; i++) {
        int s = sy * 8 + sx0 + i;
        float4* d4 = (float4*)(s_z + s * OCC + oc0);
        d4[0] = make_float4(acc[i][0], acc[i][1], acc[i][2], acc[i][3]);
        d4[1] = make_float4(acc[i][4], acc[i][5], acc[i][6], acc[i][7]);
        d4[2] = make_float4(acc[i][8], acc[i][9], acc[i][10], acc[i][11]);
    }
    __syncthreads();

    int imgt = b * TT + t;
#pragma unroll 1
    for (int k = 0; k < 12; k++) {
        int e = tid + k * 256;         // 0..3071: 64 spatial x 48 f-channels
        int s = e / 48, f = e - s * 48;
        int yy = gy0 + 1 + (s >> 3);
        int xx = gx0 + 1 + (s & 7);
        size_t zoff = (((size_t)imgt * HH + yy) * WW + xx) * OCC;
        const float* zx = g_zx + zoff;
        float zi = s_z[s * OCC + f]          + zx[f];
        float zf = s_z[s * OCC + f + NF]     + zx[f + NF];
        float zg = s_z[s * OCC + f + 2 * NF] + zx[f + 2 * NF];
        float zo = s_z[s * OCC + f + 3 * NF] + zx[f + 3 * NF];

        size_t hoff = (((size_t)b * HH + yy) * WW + xx) * NF + f;
        float cold = g_c[hoff];
        float cn = hsig(zf) * cold + hsig(zi) * tanhf(zg);
        float hn = hsig(zo) * tanhf(cn);
        g_c[hoff]  = cn;
        hout[hoff] = hn;

        size_t ooff = (((size_t)imgt * HH + yy) * WW + xx) * NF + f;
        if (LAYER == 1)
            g_h1[ooff] = hn;
        else
            out[ooff] = xres[ooff] + hn;
    }
}

extern "C" void kernel_launch(void* const* d_in, const int* in_sizes, int n_in,
                              void* d_out, int out_size) {
    const float* x     = (const float*)d_in[0];
    const float* Wx1   = (const float*)d_in[1];
    const float* Wh1   = (const float*)d_in[2];
    const float* b1    = (const float*)d_in[3];
    const float* Wx2   = (const float*)d_in[4];
    const float* Wh2   = (const float*)d_in[5];
    const float* b2    = (const float*)d_in[6];
    const float* gamma = (const float*)d_in[7];
    const float* beta  = (const float*)d_in[8];
    const float* mean  = (const float*)d_in[9];
    const float* var   = (const float*)d_in[10];
    float* out = (float*)d_out;

    cudaFuncSetAttribute((const void*)convx_kernel<false>,
                         cudaFuncAttributeMaxDynamicSharedMemorySize, SMEM_BYTES);
    cudaFuncSetAttribute((const void*)convx_kernel<true>,
                         cudaFuncAttributeMaxDynamicSharedMemorySize, SMEM_BYTES);
    cudaFuncSetAttribute((const void*)step_kernel<1>,
                         cudaFuncAttributeMaxDynamicSharedMemorySize, SMEM_BYTES);
    cudaFuncSetAttribute((const void*)step_kernel<2>,
                         cudaFuncAttributeMaxDynamicSharedMemorySize, SMEM_BYTES);

    dim3 blk(256);
    dim3 gridx(8, 8, BB * TT);  // all (b,t) images
    dim3 grids(8, 8, BB);       // one recurrent step

    // ---- Layer 1 ----
    zero_state_kernel<<<256, 256>>>();
    convx_kernel<false><<<gridx, blk, SMEM_BYTES>>>(x, Wx1, b1,
                                                    nullptr, nullptr, nullptr, nullptr);
    for (int t = 0; t < TT; t++)
        step_kernel<1><<<grids, blk, SMEM_BYTES>>>(Wh1, t, t & 1, nullptr, nullptr);

    // ---- Layer 2 (BN folded into Zx conv's input load) ----
    zero_state_kernel<<<256, 256>>>();
    convx_kernel<true><<<gridx, blk, SMEM_BYTES>>>(nullptr, Wx2, b2,
                                                   gamma, beta, mean, var);
    for (int t = 0; t < TT; t++)
        step_kernel<2><<<grids, blk, SMEM_BYTES>>>(Wh2, t, t & 1, x, out);
}

// round 16
// speedup vs baseline: 2.2417x; 1.7085x over previous
#include <cuda_runtime.h>
#include <cuda_bf16.h>

// Problem constants
#define HH   64
#define WW   64
#define CIN  48
#define OCC  192
#define BB   4
#define TT   16
#define NF   48

typedef unsigned int u32;
typedef unsigned short us16;

// smem layout (bytes): bf16 patch hi/lo planes + staged bf16 weight slice (hi+lo)
#define OFF_AH 0          // 100px * 48ch * 2B = 9600
#define OFF_AL 9600
#define OFF_W  19200      // [2][192][48] bf16 = 36864
#define SMEM_BYTES 56064  // z-phase reuses bytes [0, 49152)

// Scratch (device globals -- no runtime allocation allowed)
__device__ float g_zx[(size_t)BB * TT * HH * WW * OCC];
__device__ float g_h1[(size_t)BB * TT * HH * WW * NF];
__device__ float g_hA[(size_t)BB * HH * WW * NF];
__device__ float g_hB[(size_t)BB * HH * WW * NF];
__device__ float g_c [(size_t)BB * HH * WW * NF];
// Pre-split transposed weights: [tensor][kk][{hi,lo}][oc=192][c=48] bf16
// tensors: 0=Wx1 1=Wh1 2=Wx2 3=Wh2
__device__ us16 g_wt[4][9 * 2 * 192 * 48];

__global__ void zero_state_kernel() {
    size_t n = (size_t)BB * HH * WW * NF;
    for (size_t i = (size_t)blockIdx.x * blockDim.x + threadIdx.x; i < n;
         i += (size_t)gridDim.x * blockDim.x) {
        g_hA[i] = 0.f;
        g_c[i]  = 0.f;
    }
}

__device__ __forceinline__ float hsig(float x) {
    return __saturatef(x * (1.0f / 6.0f) + 0.5f);
}

__device__ __forceinline__ us16 bf16_bits(float v) {
    __nv_bfloat16 h = __float2bfloat16(v);
    return *(us16*)&h;
}

// Split weights into bf16 hi/lo, transpose [kk][c][oc] -> [kk][{hi,lo}][oc][c].
__global__ void prep_weights(const float* __restrict__ W0, const float* __restrict__ W1,
                             const float* __restrict__ W2, const float* __restrict__ W3) {
    const float* src = (blockIdx.y == 0) ? W0 : (blockIdx.y == 1) ? W1
                     : (blockIdx.y == 2) ? W2 : W3;
    int e = blockIdx.x * 256 + threadIdx.x;
    if (e >= 9 * 48 * 192) return;
    int kk = e / (48 * 192);
    int r  = e - kk * 48 * 192;
    int c  = r / 192;
    int oc = r - c * 192;
    float v = src[e];
    __nv_bfloat16 h = __float2bfloat16(v);
    float hv = __bfloat162float(h);
    __nv_bfloat16 l = __float2bfloat16(v - hv);
    size_t base = (size_t)kk * 2 * 9216;
    g_wt[blockIdx.y][base + oc * 48 + c]        = *(us16*)&h;
    g_wt[blockIdx.y][base + 9216 + oc * 48 + c] = *(us16*)&l;
}

// Load 10x10x48 patch (zero-padded), split to bf16 hi/lo planes in smem.
// BN (fp32, before split) applies ONLY to in-bounds pixels.
template <bool BN>
__device__ __forceinline__ void load_patch(const float* __restrict__ src,
                                           us16* s_ah, us16* s_al,
                                           int gy0, int gx0, int tid,
                                           const float* s_scale, const float* s_shift) {
    for (int p = tid; p < 1200; p += 256) {  // 100 pixels * 12 float4
        int pix = p / 12, cv = p - pix * 12;
        int py = pix / 10, px = pix - py * 10;
        int gy = gy0 + py, gx = gx0 + px;
        float4 v = make_float4(0.f, 0.f, 0.f, 0.f);
        if ((unsigned)gy < HH && (unsigned)gx < WW) {
            v = *(const float4*)(src + ((size_t)gy * WW + gx) * CIN + cv * 4);
            if (BN) {
                int c = cv * 4;
                v.x = v.x * s_scale[c + 0] + s_shift[c + 0];
                v.y = v.y * s_scale[c + 1] + s_shift[c + 1];
                v.z = v.z * s_scale[c + 2] + s_shift[c + 2];
                v.w = v.w * s_scale[c + 3] + s_shift[c + 3];
            }
        }
        float vv[4] = {v.x, v.y, v.z, v.w};
        int base = pix * 48 + cv * 4;
#pragma unroll
        for (int i = 0; i < 4; i++) {
            __nv_bfloat16 h = __float2bfloat16(vv[i]);
            float hv = __bfloat162float(h);
            __nv_bfloat16 l = __float2bfloat16(vv[i] - hv);
            s_ah[base + i] = *(us16*)&h;
            s_al[base + i] = *(us16*)&l;
        }
    }
}

__device__ __forceinline__ void mma16816(float c[4], u32 a0, u32 a1, u32 a2, u32 a3,
                                         u32 b0, u32 b1) {
    asm volatile(
        "mma.sync.aligned.m16n8k16.row.col.f32.bf16.bf16.f32 "
        "{%0,%1,%2,%3},{%4,%5,%6,%7},{%8,%9},{%0,%1,%2,%3};"
        : "+f"(c[0]), "+f"(c[1]), "+f"(c[2]), "+f"(c[3])
        : "r"(a0), "r"(a1), "r"(a2), "r"(a3), "r"(b0), "r"(b1));
}

// 27-chunk MMA mainloop over one patch + one pre-split weight tensor.
// acc[j][0..3]: j = n-tile (oc tile nb+8j); C rows = pixels mt*16+g / +8.
__device__ __forceinline__ void conv_mma(const us16* wt,  // g_wt[sel]
                                         char* smem, float acc[12][4],
                                         int tid, int mt, int nb, int g, int t) {
    us16* s_ah = (us16*)(smem + OFF_AH);
    us16* s_al = (us16*)(smem + OFF_AL);
    us16* s_w  = (us16*)(smem + OFF_W);

    int p0 = mt * 16 + g;
    int py0 = p0 >> 3, px0 = p0 & 7;

#pragma unroll 1
    for (int kk = 0; kk < 9; kk++) {
        __syncthreads();
        // stage hi+lo weight slice: 36864 B = 2304 float4, 9 per thread
        const float4* wsrc = (const float4*)(wt + (size_t)kk * 2 * 9216);
        float4* wdst = (float4*)s_w;
#pragma unroll
        for (int p = 0; p < 9; p++) wdst[tid + p * 256] = wsrc[tid + p * 256];
        __syncthreads();

        int kh = kk / 3, kw = kk - kh * 3;
        int aro = ((py0 + kh) * 10 + px0 + kw) * 48 + 2 * t;
#pragma unroll
        for (int ci = 0; ci < 3; ci++) {
            int ai = aro + ci * 16;
            u32 ah0 = *(u32*)(s_ah + ai),       ah1 = *(u32*)(s_ah + ai + 480);
            u32 ah2 = *(u32*)(s_ah + ai + 8),   ah3 = *(u32*)(s_ah + ai + 488);
            u32 al0 = *(u32*)(s_al + ai),       al1 = *(u32*)(s_al + ai + 480);
            u32 al2 = *(u32*)(s_al + ai + 8),   al3 = *(u32*)(s_al + ai + 488);
#pragma unroll
            for (int j = 0; j < 12; j++) {
                int wi = (nb + 8 * j + g) * 48 + ci * 16 + 2 * t;
                u32 bh0 = *(u32*)(s_w + wi),        bh1 = *(u32*)(s_w + wi + 8);
                u32 bl0 = *(u32*)(s_w + 9216 + wi), bl1 = *(u32*)(s_w + 9216 + wi + 8);
                mma16816(acc[j], ah0, ah1, ah2, ah3, bh0, bh1);
                mma16816(acc[j], ah0, ah1, ah2, ah3, bl0, bl1);
                mma16816(acc[j], al0, al1, al2, al3, bh0, bh1);
            }
        }
    }
}

// conv(input, W[sel]) + b over all 64 (b,t) frames -> g_zx. BN=true: input = bn(g_h1).
template <bool BN>
__global__ void __launch_bounds__(256, 2) convx_kernel(
    const float* __restrict__ xin, int wsel, const float* __restrict__ bias,
    const float* __restrict__ gamma, const float* __restrict__ beta,
    const float* __restrict__ mean, const float* __restrict__ var) {
    extern __shared__ char smem[];
    __shared__ float s_scale[CIN], s_shift[CIN];

    int tid = threadIdx.x;
    int img = blockIdx.z;
    int gy0 = blockIdx.y * 8 - 1, gx0 = blockIdx.x * 8 - 1;
    int wid = tid >> 5, lane = tid & 31;
    int g = lane >> 2, t = lane & 3;
    int mt = wid & 3, nb = (wid >> 2) * 96;

    if (BN) {
        if (tid < CIN) {
            float sc = gamma[tid] * rsqrtf(var[tid] + 1e-3f);
            s_scale[tid] = sc;
            s_shift[tid] = beta[tid] - mean[tid] * sc;
        }
        __syncthreads();
    }
    const float* src = BN ? (g_h1 + (size_t)img * HH * WW * NF)
                          : (xin + (size_t)img * HH * WW * CIN);
    load_patch<BN>(src, (us16*)(smem + OFF_AH), (us16*)(smem + OFF_AL),
                   gy0, gx0, tid, s_scale, s_shift);

    float acc[12][4];
#pragma unroll
    for (int j = 0; j < 12; j++) {
        float b0 = bias[nb + 8 * j + 2 * t];
        float b1 = bias[nb + 8 * j + 2 * t + 1];
        acc[j][0] = b0; acc[j][1] = b1; acc[j][2] = b0; acc[j][3] = b1;
    }

    conv_mma(g_wt[wsel], smem, acc, tid, mt, nb, g, t);

    // write to smem z then coalesced store
    __syncthreads();
    float* s_z = (float*)smem;
    int p0 = mt * 16 + g;
#pragma unroll
    for (int j = 0; j < 12; j++) {
        int oc = nb + 8 * j + 2 * t;
        *(float2*)(s_z + p0 * OCC + oc)       = make_float2(acc[j][0], acc[j][1]);
        *(float2*)(s_z + (p0 + 8) * OCC + oc) = make_float2(acc[j][2], acc[j][3]);
    }
    __syncthreads();

    // 64 px * 192 = 12288 floats = 3072 float4; 12 per thread
    int y0 = blockIdx.y * 8, x0 = blockIdx.x * 8;
#pragma unroll
    for (int k = 0; k < 12; k++) {
        int idx = tid + k * 256;          // float4 index
        int r = idx / 384, col = idx - r * 384;  // row r, 384 float4 per row (8px*192)
        float4 v = ((float4*)s_z)[idx];
        float* dst = g_zx + (((size_t)img * HH + y0 + r) * WW + x0) * OCC;
        ((float4*)dst)[col] = v;
    }
}

// One recurrent step: z = zx[t] + conv(h, Wh[sel]); gates; update c,h.
template <int LAYER>
__global__ void __launch_bounds__(256, 2) step_kernel(
    int wsel, int t, int parity,
    const float* __restrict__ xres, float* __restrict__ out) {
    extern __shared__ char smem[];
    int tid = threadIdx.x;
    int b = blockIdx.z;
    int gy0 = blockIdx.y * 8 - 1, gx0 = blockIdx.x * 8 - 1;
    int wid = tid >> 5, lane = tid & 31;
    int g = lane >> 2, tq = lane & 3;
    int mt = wid & 3, nb = (wid >> 2) * 96;

    const float* hin = parity ? g_hB : g_hA;
    float* hout      = parity ? g_hA : g_hB;

    load_patch<false>(hin + (size_t)b * HH * WW * NF,
                      (us16*)(smem + OFF_AH), (us16*)(smem + OFF_AL),
                      gy0, gx0, tid, nullptr, nullptr);

    float acc[12][4];
#pragma unroll
    for (int j = 0; j < 12; j++) {
        acc[j][0] = 0.f; acc[j][1] = 0.f; acc[j][2] = 0.f; acc[j][3] = 0.f;
    }

    conv_mma(g_wt[wsel], smem, acc, tid, mt, nb, g, tq);

    __syncthreads();
    float* s_z = (float*)smem;
    int p0 = mt * 16 + g;
#pragma unroll
    for (int j = 0; j < 12; j++) {
        int oc = nb + 8 * j + 2 * tq;
        *(float2*)(s_z + p0 * OCC + oc)       = make_float2(acc[j][0], acc[j][1]);
        *(float2*)(s_z + (p0 + 8) * OCC + oc) = make_float2(acc[j][2], acc[j][3]);
    }
    __syncthreads();

    int imgt = b * TT + t;
#pragma unroll 1
    for (int k = 0; k < 12; k++) {
        int e = tid + k * 256;         // 0..3071: 64 spatial x 48 f-channels
        int s = e / 48, f = e - s * 48;
        int yy = gy0 + 1 + (s >> 3);
        int xx = gx0 + 1 + (s & 7);
        size_t zoff = (((size_t)imgt * HH + yy) * WW + xx) * OCC;
        const float* zx = g_zx + zoff;
        float zi = s_z[s * OCC + f]          + zx[f];
        float zf = s_z[s * OCC + f + NF]     + zx[f + NF];
        float zg = s_z[s * OCC + f + 2 * NF] + zx[f + 2 * NF];
        float zo = s_z[s * OCC + f + 3 * NF] + zx[f + 3 * NF];

        size_t hoff = (((size_t)b * HH + yy) * WW + xx) * NF + f;
        float cold = g_c[hoff];
        float cn = hsig(zf) * cold + hsig(zi) * tanhf(zg);
        float hn = hsig(zo) * tanhf(cn);
        g_c[hoff]  = cn;
        hout[hoff] = hn;

        size_t ooff = (((size_t)imgt * HH + yy) * WW + xx) * NF + f;
        if (LAYER == 1)
            g_h1[ooff] = hn;
        else
            out[ooff] = xres[ooff] + hn;
    }
}

extern "C" void kernel_launch(void* const* d_in, const int* in_sizes, int n_in,
                              void* d_out, int out_size) {
    const float* x     = (const float*)d_in[0];
    const float* Wx1   = (const float*)d_in[1];
    const float* Wh1   = (const float*)d_in[2];
    const float* b1    = (const float*)d_in[3];
    const float* Wx2   = (const float*)d_in[4];
    const float* Wh2   = (const float*)d_in[5];
    const float* b2    = (const float*)d_in[6];
    const float* gamma = (const float*)d_in[7];
    const float* beta  = (const float*)d_in[8];
    const float* mean  = (const float*)d_in[9];
    const float* var   = (const float*)d_in[10];
    float* out = (float*)d_out;

    cudaFuncSetAttribute((const void*)convx_kernel<false>,
                         cudaFuncAttributeMaxDynamicSharedMemorySize, SMEM_BYTES);
    cudaFuncSetAttribute((const void*)convx_kernel<true>,
                         cudaFuncAttributeMaxDynamicSharedMemorySize, SMEM_BYTES);
    cudaFuncSetAttribute((const void*)step_kernel<1>,
                         cudaFuncAttributeMaxDynamicSharedMemorySize, SMEM_BYTES);
    cudaFuncSetAttribute((const void*)step_kernel<2>,
                         cudaFuncAttributeMaxDynamicSharedMemorySize, SMEM_BYTES);

    dim3 blk(256);
    dim3 gridp((9 * 48 * 192 + 255) / 256, 4);
    dim3 gridx(8, 8, BB * TT);
    dim3 grids(8, 8, BB);

    zero_state_kernel<<<256, 256>>>();
    prep_weights<<<gridp, blk>>>(Wx1, Wh1, Wx2, Wh2);

    // ---- Layer 1 ----
    convx_kernel<false><<<gridx, blk, SMEM_BYTES>>>(x, 0, b1,
                                                    nullptr, nullptr, nullptr, nullptr);
    for (int t = 0; t < TT; t++)
        step_kernel<1><<<grids, blk, SMEM_BYTES>>>(1, t, t & 1, nullptr, nullptr);

    // ---- Layer 2 (BN folded into Zx conv's patch load, fp32 pre-split) ----
    zero_state_kernel<<<256, 256>>>();
    convx_kernel<true><<<gridx, blk, SMEM_BYTES>>>(nullptr, 2, b2,
                                                   gamma, beta, mean, var);
    for (int t = 0; t < TT; t++)
        step_kernel<2><<<grids, blk, SMEM_BYTES>>>(3, t, t & 1, x, out);
}